// round 1
// baseline (speedup 1.0000x reference)
#include <cuda_runtime.h>
#include <cstdint>

#define SEQ   4096
#define HD    64
#define NB    4
#define TQ    64
#define TN    64
#define PAD   68              // smem row stride (floats): 68 mod 32 = 4 -> conflict-free frag loads
#define NIT   (SEQ / TN)      // 64
#define INV_T 0.125f          // 1/temperature

// Row sums of exp(scores) — scratch between the two passes.
__device__ float g_sums[NB * SEQ];

__device__ __forceinline__ uint32_t f2tf(float x) {
    uint32_t u;
    asm("cvt.rna.tf32.f32 %0, %1;" : "=r"(u) : "f"(x));
    return u;
}
__device__ __forceinline__ float tf32r(float x) { return __uint_as_float(f2tf(x)); }

__device__ __forceinline__ void mma8(float c[4], const uint32_t a[4], const uint32_t b[2]) {
    asm volatile(
        "mma.sync.aligned.m16n8k8.row.col.f32.tf32.tf32.f32 "
        "{%0,%1,%2,%3}, {%4,%5,%6,%7}, {%8,%9}, {%0,%1,%2,%3};\n"
        : "+f"(c[0]), "+f"(c[1]), "+f"(c[2]), "+f"(c[3])
        : "r"(a[0]), "r"(a[1]), "r"(a[2]), "r"(a[3]), "r"(b[0]), "r"(b[1]));
}

// Stage a 64x64 fp32 tile (row-major, ld=HD) into smem (ld=PAD), rounding to tf32.
__device__ __forceinline__ void stage_tile(float* dst, const float* __restrict__ src, int tid) {
#pragma unroll
    for (int t = 0; t < 8; ++t) {
        int idx = tid + t * 128;
        int r = idx >> 4, c4 = (idx & 15) << 2;
        float4 v = *reinterpret_cast<const float4*>(src + r * HD + c4);
        float4 w = make_float4(tf32r(v.x), tf32r(v.y), tf32r(v.z), tf32r(v.w));
        *reinterpret_cast<float4*>(dst + r * PAD + c4) = w;
    }
}

// Warp-tile (32x32) QK^T: C[q][n] = sum_d Q[q][d] * K[n][d]
__device__ __forceinline__ void qk_mma(float c[2][4][4], const float* Qs, const float* Ks,
                                       int wq, int wn, int g, int tg) {
#pragma unroll
    for (int kk = 0; kk < 8; ++kk) {
        const int k0 = kk * 8;
        uint32_t a[2][4];
#pragma unroll
        for (int i = 0; i < 2; ++i) {
            const int r = wq + i * 16 + g;
            a[i][0] = __float_as_uint(Qs[r * PAD + k0 + tg]);
            a[i][1] = __float_as_uint(Qs[(r + 8) * PAD + k0 + tg]);
            a[i][2] = __float_as_uint(Qs[r * PAD + k0 + tg + 4]);
            a[i][3] = __float_as_uint(Qs[(r + 8) * PAD + k0 + tg + 4]);
        }
#pragma unroll
        for (int j = 0; j < 4; ++j) {
            const int n = wn + j * 8 + g;
            uint32_t bb[2];
            bb[0] = __float_as_uint(Ks[n * PAD + k0 + tg]);
            bb[1] = __float_as_uint(Ks[n * PAD + k0 + tg + 4]);
#pragma unroll
            for (int i = 0; i < 2; ++i) mma8(c[i][j], a[i], bb);
        }
    }
}

// Warp-tile (32x32) AV: O[q][d] += sum_k P[q][k] * V[k][d]
__device__ __forceinline__ void av_mma(float o[2][4][4], const float* Ps, const float* Vs,
                                       int wq, int wn, int g, int tg) {
#pragma unroll
    for (int kk = 0; kk < 8; ++kk) {
        const int k0 = kk * 8;
        uint32_t a[2][4];
#pragma unroll
        for (int i = 0; i < 2; ++i) {
            const int r = wq + i * 16 + g;
            a[i][0] = __float_as_uint(Ps[r * PAD + k0 + tg]);
            a[i][1] = __float_as_uint(Ps[(r + 8) * PAD + k0 + tg]);
            a[i][2] = __float_as_uint(Ps[r * PAD + k0 + tg + 4]);
            a[i][3] = __float_as_uint(Ps[(r + 8) * PAD + k0 + tg + 4]);
        }
#pragma unroll
        for (int j = 0; j < 4; ++j) {
            uint32_t bb[2];
            bb[0] = __float_as_uint(Vs[(k0 + tg) * PAD + wn + j * 8 + g]);
            bb[1] = __float_as_uint(Vs[(k0 + tg + 4) * PAD + wn + j * 8 + g]);
#pragma unroll
            for (int i = 0; i < 2; ++i) mma8(o[i][j], a[i], bb);
        }
    }
}

// ---------------- Pass 1: row sums of exp(scores) ----------------
__global__ void __launch_bounds__(128) attn_sums_kernel(const float* __restrict__ Q,
                                                        const float* __restrict__ K) {
    __shared__ float Qs[TQ * PAD];
    __shared__ float Ks[TN * PAD];
    __shared__ float rowsum_s[TQ];

    const int b = blockIdx.y;
    const int q0 = blockIdx.x * TQ;
    const int tid = threadIdx.x;
    const int warp = tid >> 5, lane = tid & 31;
    const int g = lane >> 2, tg = lane & 3;
    const int wq = (warp >> 1) * 32;
    const int wn = (warp & 1) * 32;

    const float* Qb = Q + ((size_t)b * SEQ + q0) * HD;
    const float* Kb = K + (size_t)b * SEQ * HD;

    if (tid < TQ) rowsum_s[tid] = 0.f;
    stage_tile(Qs, Qb, tid);

    float rsum[2][2] = {{0.f, 0.f}, {0.f, 0.f}};

    for (int it = 0; it < NIT; ++it) {
        __syncthreads();
        stage_tile(Ks, Kb + (size_t)it * TN * HD, tid);
        __syncthreads();

        float c[2][4][4] = {};
        qk_mma(c, Qs, Ks, wq, wn, g, tg);

#pragma unroll
        for (int i = 0; i < 2; ++i)
#pragma unroll
            for (int j = 0; j < 4; ++j) {
                rsum[i][0] += __expf(c[i][j][0] * INV_T) + __expf(c[i][j][1] * INV_T);
                rsum[i][1] += __expf(c[i][j][2] * INV_T) + __expf(c[i][j][3] * INV_T);
            }
    }

#pragma unroll
    for (int i = 0; i < 2; ++i)
#pragma unroll
        for (int h = 0; h < 2; ++h) {
            float v = rsum[i][h];
            v += __shfl_xor_sync(0xffffffffu, v, 1);
            v += __shfl_xor_sync(0xffffffffu, v, 2);
            if (tg == 0) atomicAdd(&rowsum_s[wq + i * 16 + h * 8 + g], v);
        }
    __syncthreads();
    if (tid < TQ) g_sums[b * SEQ + q0 + tid] = rowsum_s[tid];
}

// ---------------- Pass 2: attn + out ----------------
extern __shared__ float smemB[];  // Qs[TQ*PAD] | KPs[TN*PAD] (K tile, then reused for P) | Vs[TN*PAD]

__global__ void __launch_bounds__(128) attn_main_kernel(const float* __restrict__ Q,
                                                        const float* __restrict__ K,
                                                        const float* __restrict__ V,
                                                        float* __restrict__ outp,
                                                        float* __restrict__ attnp) {
    float* Qs  = smemB;
    float* KPs = smemB + TQ * PAD;
    float* Vs  = KPs + TN * PAD;

    const int b = blockIdx.y;
    const int q0 = blockIdx.x * TQ;
    const int tid = threadIdx.x;
    const int warp = tid >> 5, lane = tid & 31;
    const int g = lane >> 2, tg = lane & 3;
    const int wq = (warp >> 1) * 32;
    const int wn = (warp & 1) * 32;

    const float* Qb = Q + ((size_t)b * SEQ + q0) * HD;
    const float* Kb = K + (size_t)b * SEQ * HD;
    const float* Vb = V + (size_t)b * SEQ * HD;

    // reciprocals of row sums for this thread's 4 rows
    float rinv[2][2];
#pragma unroll
    for (int i = 0; i < 2; ++i)
#pragma unroll
        for (int h = 0; h < 2; ++h)
            rinv[i][h] = 1.0f / g_sums[b * SEQ + q0 + wq + i * 16 + h * 8 + g];

    stage_tile(Qs, Qb, tid);

    float o[2][4][4] = {};

    for (int it = 0; it < NIT; ++it) {
        const int n0 = it * TN;
        __syncthreads();                           // prev iter's AV/attn done with KPs/Vs
        stage_tile(KPs, Kb + (size_t)n0 * HD, tid);
        stage_tile(Vs,  Vb + (size_t)n0 * HD, tid);
        __syncthreads();

        float c[2][4][4] = {};
        qk_mma(c, Qs, KPs, wq, wn, g, tg);

        // p = exp(s/T) / rowsum ; write attn directly from fragments (full fp32)
        float p[2][4][4];
#pragma unroll
        for (int i = 0; i < 2; ++i) {
            const int row = q0 + wq + i * 16 + g;
            float* ar = attnp + (size_t)b * SEQ * SEQ + (size_t)row * SEQ + n0 + wn;
#pragma unroll
            for (int j = 0; j < 4; ++j) {
                p[i][j][0] = __expf(c[i][j][0] * INV_T) * rinv[i][0];
                p[i][j][1] = __expf(c[i][j][1] * INV_T) * rinv[i][0];
                p[i][j][2] = __expf(c[i][j][2] * INV_T) * rinv[i][1];
                p[i][j][3] = __expf(c[i][j][3] * INV_T) * rinv[i][1];
                *reinterpret_cast<float2*>(ar + j * 8 + 2 * tg) =
                    make_float2(p[i][j][0], p[i][j][1]);
                *reinterpret_cast<float2*>(ar + (size_t)8 * SEQ + j * 8 + 2 * tg) =
                    make_float2(p[i][j][2], p[i][j][3]);
            }
        }

        __syncthreads();   // all warps done reading K tile before P overwrites it

        // store tf32-rounded P into KPs for the AV mma
#pragma unroll
        for (int i = 0; i < 2; ++i) {
            const int r = wq + i * 16 + g;
#pragma unroll
            for (int j = 0; j < 4; ++j) {
                const int col = wn + j * 8 + 2 * tg;
                *reinterpret_cast<uint2*>(&KPs[r * PAD + col]) =
                    make_uint2(f2tf(p[i][j][0]), f2tf(p[i][j][1]));
                *reinterpret_cast<uint2*>(&KPs[(r + 8) * PAD + col]) =
                    make_uint2(f2tf(p[i][j][2]), f2tf(p[i][j][3]));
            }
        }

        __syncthreads();   // P tile ready for cross-warp reads

        av_mma(o, KPs, Vs, wq, wn, g, tg);
    }

    // write out [B,S,64]
#pragma unroll
    for (int i = 0; i < 2; ++i) {
        const int row = q0 + wq + i * 16 + g;
        float* orow = outp + ((size_t)b * SEQ + row) * HD;
#pragma unroll
        for (int j = 0; j < 4; ++j) {
            const int col = wn + j * 8 + 2 * tg;
            *reinterpret_cast<float2*>(orow + col)          = make_float2(o[i][j][0], o[i][j][1]);
            *reinterpret_cast<float2*>(orow + 8 * HD + col) = make_float2(o[i][j][2], o[i][j][3]);
        }
    }
}

extern "C" void kernel_launch(void* const* d_in, const int* in_sizes, int n_in,
                              void* d_out, int out_size) {
    const float* q = (const float*)d_in[0];
    const float* k = (const float*)d_in[1];
    const float* v = (const float*)d_in[2];
    float* outp  = (float*)d_out;
    float* attnp = outp + (size_t)NB * SEQ * HD;

    const int smem_bytes = 3 * TN * PAD * (int)sizeof(float);  // 52224
    cudaFuncSetAttribute(attn_main_kernel,
                         cudaFuncAttributeMaxDynamicSharedMemorySize, smem_bytes);

    dim3 grid(SEQ / TQ, NB);
    attn_sums_kernel<<<grid, 128>>>(q, k);
    attn_main_kernel<<<grid, 128, smem_bytes>>>(q, k, v, outp, attnp);
}

// round 3
// speedup vs baseline: 1.0402x; 1.0402x over previous
#include <cuda_runtime.h>
#include <cstdint>

#define SEQ 4096
#define HD 64
#define NBATCH 4
#define TN 64
#define NIT (SEQ / TN)
#define PAD 68
#define NTH 256
#define CEXP 0.18033688011112042f  // log2(e) / temperature(8)

// smem float offsets
#define O_QP 0        // Q tile (prologue) then P tile (phase B): 128*68
#define O_K0 8704
#define O_K1 13056
#define O_V0 17408
#define O_V1 21760
#define O_RS 26112    // 128 rowsums
#define SMEM_BYTES (26240 * 4)

__device__ __forceinline__ uint32_t f2tf(float x) {
    uint32_t u;
    asm("cvt.rna.tf32.f32 %0, %1;" : "=r"(u) : "f"(x));
    return u;
}

__device__ __forceinline__ void mma8(float c[4], const uint32_t a[4], const uint32_t b[2]) {
    asm volatile(
        "mma.sync.aligned.m16n8k8.row.col.f32.tf32.tf32.f32 "
        "{%0,%1,%2,%3}, {%4,%5,%6,%7}, {%8,%9}, {%0,%1,%2,%3};\n"
        : "+f"(c[0]), "+f"(c[1]), "+f"(c[2]), "+f"(c[3])
        : "r"(a[0]), "r"(a[1]), "r"(a[2]), "r"(a[3]), "r"(b[0]), "r"(b[1]));
}

__global__ void __launch_bounds__(NTH, 1)
attn_fused(const float* __restrict__ Q, const float* __restrict__ K,
           const float* __restrict__ V, float* __restrict__ outp,
           float* __restrict__ attnp) {
    extern __shared__ float sm[];
    const int tid = threadIdx.x, w = tid >> 5, lane = tid & 31;
    const int g = lane >> 2, tg = lane & 3;
    const int b = blockIdx.x >> 5;
    const int q0 = (blockIdx.x & 31) << 7;  // 128-row q tile
    const int wq = (w >> 1) * 32, wn = (w & 1) * 32;

    const float* Qb = Q + ((size_t)b * SEQ + q0) * HD;
    const float* Kb = K + (size_t)b * SEQ * HD;
    const float* Vb = V + (size_t)b * SEQ * HD;

    float* QP = sm + O_QP;
    float* RS = sm + O_RS;
    float* KsA[2] = {sm + O_K0, sm + O_K1};
    float* VsA[2] = {sm + O_V0, sm + O_V1};

    if (tid < 128) RS[tid] = 0.f;

    // ---- stage Q tile (128x64, tf32-rounded, PAD layout) ----
#pragma unroll
    for (int t = 0; t < 8; ++t) {
        int idx = tid + t * NTH;
        int r = idx >> 4, c4 = (idx & 15) << 2;
        float4 v = *reinterpret_cast<const float4*>(Qb + r * HD + c4);
        *reinterpret_cast<uint4*>(QP + r * PAD + c4) =
            make_uint4(f2tf(v.x), f2tf(v.y), f2tf(v.z), f2tf(v.w));
    }
    __syncthreads();

    // ---- hoist Q fragments into registers (loop-invariant) ----
    uint32_t qf[8][2][4];
#pragma unroll
    for (int kk = 0; kk < 8; ++kk) {
        const int k0 = kk * 8;
#pragma unroll
        for (int i = 0; i < 2; ++i) {
            const int r = wq + i * 16 + g;
            qf[kk][i][0] = __float_as_uint(QP[r * PAD + k0 + tg]);
            qf[kk][i][1] = __float_as_uint(QP[(r + 8) * PAD + k0 + tg]);
            qf[kk][i][2] = __float_as_uint(QP[r * PAD + k0 + tg + 4]);
            qf[kk][i][3] = __float_as_uint(QP[(r + 8) * PAD + k0 + tg + 4]);
        }
    }

    float4 kr[4], vr[4];
    auto ldg64 = [&](const float* src, int n0, float4 rr[4]) {
#pragma unroll
        for (int t = 0; t < 4; ++t) {
            int idx = tid + t * NTH;
            int r = idx >> 4, c4 = (idx & 15) << 2;
            rr[t] = *reinterpret_cast<const float4*>(src + (size_t)(n0 + r) * HD + c4);
        }
    };
    auto sts64 = [&](float* dst, const float4 rr[4]) {
#pragma unroll
        for (int t = 0; t < 4; ++t) {
            int idx = tid + t * NTH;
            int r = idx >> 4, c4 = (idx & 15) << 2;
            *reinterpret_cast<uint4*>(dst + r * PAD + c4) =
                make_uint4(f2tf(rr[t].x), f2tf(rr[t].y), f2tf(rr[t].z), f2tf(rr[t].w));
        }
    };

    // ================= Phase A: rowsums of exp =================
    ldg64(Kb, 0, kr);
    sts64(KsA[0], kr);
    __syncthreads();
    ldg64(Kb, TN, kr);

    float rsum[2][2] = {{0.f, 0.f}, {0.f, 0.f}};
    for (int it = 0; it < NIT; ++it) {
        const int s = it & 1;
        const float* Ks = KsA[s];
        float c[2][4][4] = {};
#pragma unroll
        for (int kk = 0; kk < 8; ++kk) {
            const int k0 = kk * 8;
#pragma unroll
            for (int j = 0; j < 4; ++j) {
                const int n = wn + j * 8 + g;
                uint32_t bb[2] = {__float_as_uint(Ks[n * PAD + k0 + tg]),
                                  __float_as_uint(Ks[n * PAD + k0 + tg + 4])};
                mma8(c[0][j], qf[kk][0], bb);
                mma8(c[1][j], qf[kk][1], bb);
            }
        }
#pragma unroll
        for (int i = 0; i < 2; ++i)
#pragma unroll
            for (int j = 0; j < 4; ++j) {
                rsum[i][0] += exp2f(c[i][j][0] * CEXP) + exp2f(c[i][j][1] * CEXP);
                rsum[i][1] += exp2f(c[i][j][2] * CEXP) + exp2f(c[i][j][3] * CEXP);
            }
        if (it + 1 < NIT) sts64(KsA[s ^ 1], kr);
        if (it + 2 < NIT) ldg64(Kb, (it + 2) * TN, kr);
        __syncthreads();
    }
#pragma unroll
    for (int i = 0; i < 2; ++i)
#pragma unroll
        for (int h = 0; h < 2; ++h) {
            float v = rsum[i][h];
            v += __shfl_xor_sync(0xffffffffu, v, 1);
            v += __shfl_xor_sync(0xffffffffu, v, 2);
            if (tg == 0) atomicAdd(&RS[wq + i * 16 + h * 8 + g], v);
        }
    __syncthreads();
    float rinv[2][2];
#pragma unroll
    for (int i = 0; i < 2; ++i)
#pragma unroll
        for (int h = 0; h < 2; ++h) rinv[i][h] = 1.0f / RS[wq + i * 16 + h * 8 + g];
    __syncthreads();

    // ================= Phase B: attn + AV =================
    float o[2][4][4] = {};
    ldg64(Kb, 0, kr);
    ldg64(Vb, 0, vr);
    sts64(KsA[0], kr);
    sts64(VsA[0], vr);
    __syncthreads();
    ldg64(Kb, TN, kr);
    ldg64(Vb, TN, vr);

    for (int it = 0; it < NIT; ++it) {
        const int s = it & 1;
        const int n0 = it * TN;
        const float* Ks = KsA[s];
        float c[2][4][4] = {};
#pragma unroll
        for (int kk = 0; kk < 8; ++kk) {
            const int k0 = kk * 8;
#pragma unroll
            for (int j = 0; j < 4; ++j) {
                const int n = wn + j * 8 + g;
                uint32_t bb[2] = {__float_as_uint(Ks[n * PAD + k0 + tg]),
                                  __float_as_uint(Ks[n * PAD + k0 + tg + 4])};
                mma8(c[0][j], qf[kk][0], bb);
                mma8(c[1][j], qf[kk][1], bb);
            }
        }

        // normalized probabilities (in-place in c) + attn store
#pragma unroll
        for (int i = 0; i < 2; ++i) {
            const int row = q0 + wq + i * 16 + g;
            float* ar = attnp + ((size_t)b * SEQ + row) * SEQ + n0 + wn;
#pragma unroll
            for (int j = 0; j < 4; ++j) {
                c[i][j][0] = exp2f(c[i][j][0] * CEXP) * rinv[i][0];
                c[i][j][1] = exp2f(c[i][j][1] * CEXP) * rinv[i][0];
                c[i][j][2] = exp2f(c[i][j][2] * CEXP) * rinv[i][1];
                c[i][j][3] = exp2f(c[i][j][3] * CEXP) * rinv[i][1];
                *reinterpret_cast<float2*>(ar + j * 8 + 2 * tg) =
                    make_float2(c[i][j][0], c[i][j][1]);
                *reinterpret_cast<float2*>(ar + (size_t)8 * SEQ + j * 8 + 2 * tg) =
                    make_float2(c[i][j][2], c[i][j][3]);
            }
        }

        __syncthreads();  // all warps done av(it-1): P buffer reusable

        // store tf32 P into QP (PAD layout)
#pragma unroll
        for (int i = 0; i < 2; ++i) {
            const int r = wq + i * 16 + g;
#pragma unroll
            for (int j = 0; j < 4; ++j) {
                const int col = wn + j * 8 + 2 * tg;
                *reinterpret_cast<uint2*>(&QP[r * PAD + col]) =
                    make_uint2(f2tf(c[i][j][0]), f2tf(c[i][j][1]));
                *reinterpret_cast<uint2*>(&QP[(r + 8) * PAD + col]) =
                    make_uint2(f2tf(c[i][j][2]), f2tf(c[i][j][3]));
            }
        }
        if (it + 1 < NIT) {
            sts64(KsA[s ^ 1], kr);
            sts64(VsA[s ^ 1], vr);
        }
        if (it + 2 < NIT) {
            ldg64(Kb, (it + 2) * TN, kr);
            ldg64(Vb, (it + 2) * TN, vr);
        }
        __syncthreads();  // P + next K/V staged

        // AV: O += P @ V
        const float* Vs = VsA[s];
#pragma unroll
        for (int kk = 0; kk < 8; ++kk) {
            const int k0 = kk * 8;
            uint32_t a[2][4];
#pragma unroll
            for (int i = 0; i < 2; ++i) {
                const int r = wq + i * 16 + g;
                a[i][0] = __float_as_uint(QP[r * PAD + k0 + tg]);
                a[i][1] = __float_as_uint(QP[(r + 8) * PAD + k0 + tg]);
                a[i][2] = __float_as_uint(QP[r * PAD + k0 + tg + 4]);
                a[i][3] = __float_as_uint(QP[(r + 8) * PAD + k0 + tg + 4]);
            }
#pragma unroll
            for (int j = 0; j < 4; ++j) {
                uint32_t bb[2] = {
                    __float_as_uint(Vs[(k0 + tg) * PAD + wn + j * 8 + g]),
                    __float_as_uint(Vs[(k0 + tg + 4) * PAD + wn + j * 8 + g])};
                mma8(o[0][j], a[0], bb);
                mma8(o[1][j], a[1], bb);
            }
        }
    }

    // ---- epilogue: write out [B,S,64] ----
#pragma unroll
    for (int i = 0; i < 2; ++i) {
        const int row = q0 + wq + i * 16 + g;
        float* orow = outp + ((size_t)b * SEQ + row) * HD;
#pragma unroll
        for (int j = 0; j < 4; ++j) {
            const int col = wn + j * 8 + 2 * tg;
            *reinterpret_cast<float2*>(orow + col) = make_float2(o[i][j][0], o[i][j][1]);
            *reinterpret_cast<float2*>(orow + 8 * HD + col) =
                make_float2(o[i][j][2], o[i][j][3]);
        }
    }
}

extern "C" void kernel_launch(void* const* d_in, const int* in_sizes, int n_in,
                              void* d_out, int out_size) {
    const float* q = (const float*)d_in[0];
    const float* k = (const float*)d_in[1];
    const float* v = (const float*)d_in[2];
    float* outp = (float*)d_out;
    float* attnp = outp + (size_t)NBATCH * SEQ * HD;

    cudaFuncSetAttribute(attn_fused, cudaFuncAttributeMaxDynamicSharedMemorySize,
                         SMEM_BYTES);
    attn_fused<<<NBATCH * 32, NTH, SMEM_BYTES>>>(q, k, v, outp, attnp);
}